// round 17
// baseline (speedup 1.0000x reference)
#include <cuda_runtime.h>
#include <math.h>

#define B 512
#define S 256
#define H 256
#define U 10
#define G4 1024   // 4*H
#define B_PERSIST 384   // batches whose enc_out slice is held L2-resident (96 MB)

// ---------------- device scratch (static allocations only) ----------------
__device__ float g_enc_out[B * S * H];   // [b][s][h]  134 MB
__device__ float g_encW1[B * U * S];     // [b][u][s]  5 MB
__device__ float g_Wenc[257 * G4];       // interleaved gate cols
__device__ float g_Wdec[513 * G4];
__device__ float g_bias_enc[G4];
__device__ float g_bias_dec[G4];
__device__ float g_hA[B * H];
__device__ float g_hB[B * H];
__device__ float g_c[B * H];
__device__ float g_ext[B * 257];         // decoder lstm extra input: [di(256) | dec_in(1)]
__device__ float g_decnext[B];           // staged teacher-forced input
__device__ float g_lossbuf[S * B];
__device__ float g_pacc[B * G4];         // dec h-half Kahan acc handoff (2 MB)
__device__ float g_pcmp[B * G4];         // dec h-half Kahan cmp handoff (2 MB)
__device__ int   g_y64;

// ---------------- cp.async helpers ------------------------------------------
__device__ __forceinline__ void cpa16(void* dst_smem, const void* src_gmem)
{
    unsigned d = (unsigned)__cvta_generic_to_shared(dst_smem);
    asm volatile("cp.async.ca.shared.global [%0], [%1], 16;" :: "r"(d), "l"(src_gmem));
}
__device__ __forceinline__ void cpa4(void* dst_smem, const void* src_gmem)
{
    unsigned d = (unsigned)__cvta_generic_to_shared(dst_smem);
    asm volatile("cp.async.ca.shared.global [%0], [%1], 4;" :: "r"(d), "l"(src_gmem));
}
#define CPA_COMMIT() asm volatile("cp.async.commit_group;" ::: "memory")
#define CPA_WAIT1()  asm volatile("cp.async.wait_group 1;" ::: "memory")
#define CPA_WAIT0()  asm volatile("cp.async.wait_group 0;" ::: "memory")

// ---------------- 256-bit L2 eviction-priority loads ------------------------
__device__ __forceinline__ void ld8_last(const float* p, float f[8])
{
    unsigned long long q0, q1, q2, q3;
    asm volatile("ld.global.nc.L2::evict_last.v4.b64 {%0,%1,%2,%3}, [%4];"
                 : "=l"(q0), "=l"(q1), "=l"(q2), "=l"(q3) : "l"(p));
    f[0] = __uint_as_float((unsigned)q0); f[1] = __uint_as_float((unsigned)(q0 >> 32));
    f[2] = __uint_as_float((unsigned)q1); f[3] = __uint_as_float((unsigned)(q1 >> 32));
    f[4] = __uint_as_float((unsigned)q2); f[5] = __uint_as_float((unsigned)(q2 >> 32));
    f[6] = __uint_as_float((unsigned)q3); f[7] = __uint_as_float((unsigned)(q3 >> 32));
}
__device__ __forceinline__ void ld8_first(const float* p, float f[8])
{
    unsigned long long q0, q1, q2, q3;
    asm volatile("ld.global.nc.L2::evict_first.v4.b64 {%0,%1,%2,%3}, [%4];"
                 : "=l"(q0), "=l"(q1), "=l"(q2), "=l"(q3) : "l"(p));
    f[0] = __uint_as_float((unsigned)q0); f[1] = __uint_as_float((unsigned)(q0 >> 32));
    f[2] = __uint_as_float((unsigned)q1); f[3] = __uint_as_float((unsigned)(q1 >> 32));
    f[4] = __uint_as_float((unsigned)q2); f[5] = __uint_as_float((unsigned)(q2 >> 32));
    f[6] = __uint_as_float((unsigned)q3); f[7] = __uint_as_float((unsigned)(q3 >> 32));
}

// ---------------- XLA-matching transcendentals -----------------------------
__device__ __forceinline__ float exp_p(float x)
{
    x = fminf(fmaxf(x, -87.0f), 87.0f);
    float t = fmaf(x, 1.44269504088896341f, 12582912.0f);
    float n = t - 12582912.0f;
    float r = fmaf(n, -0.693359375f, x);
    r = fmaf(n, 2.12194440e-4f, r);
    float p = 1.9875691500e-4f;
    p = fmaf(p, r, 1.3981999507e-3f);
    p = fmaf(p, r, 8.3334519073e-3f);
    p = fmaf(p, r, 4.1665795894e-2f);
    p = fmaf(p, r, 1.6666665459e-1f);
    p = fmaf(p, r, 5.0000001201e-1f);
    float res = fmaf(r * r, p, r) + 1.0f;
    int i = (int)n;
    float scale = __int_as_float((i + 127) << 23);
    return res * scale;
}

__device__ __forceinline__ float tanh_xla(float x)
{
    if (fabsf(x) < 0.0004f) return x;
    float xc = fminf(fmaxf(x, -7.90531110763549805f), 7.90531110763549805f);
    float x2 = xc * xc;
    float np = fmaf(x2, -2.76076847742355e-16f, 2.00018790482477e-13f);
    np = fmaf(x2, np, -8.60467152213735e-11f);
    np = fmaf(x2, np, 5.12229709037114e-08f);
    np = fmaf(x2, np, 1.48572235717979e-05f);
    np = fmaf(x2, np, 6.37261928875436e-04f);
    np = fmaf(x2, np, 4.89352455891786e-03f);
    np = np * xc;
    float dp = fmaf(x2, 1.19825839466702e-06f, 1.18534705686654e-04f);
    dp = fmaf(x2, dp, 2.26843463243900e-03f);
    dp = fmaf(x2, dp, 4.89352518554385e-03f);
    return __fdiv_rn(np, dp);
}

__device__ __forceinline__ float sig_xla(float x)
{
    return fmaf(0.5f, tanh_xla(0.5f * x), 0.5f);
}

#define KAHAN_ADD(acc, comp, val)            \
    do {                                     \
        float _y = (val) - (comp);           \
        float _t = (acc) + _y;               \
        (comp) = (_t - (acc)) - _y;          \
        (acc) = _t;                          \
    } while (0)

// ---------------- weight prep: interleave gate columns --------------------
__global__ void prep_kernel(const float* __restrict__ eWih, const float* __restrict__ eWhh,
                            const float* __restrict__ ebih, const float* __restrict__ ebhh,
                            const float* __restrict__ dWih, const float* __restrict__ dWhh,
                            const float* __restrict__ dbih, const float* __restrict__ dbhh)
{
    int idx = blockIdx.x * blockDim.x + threadIdx.x;
    if (idx >= 513 * G4) return;
    int k = idx >> 10, j = idx & 1023;
    int h = j >> 2, g = j & 3;
    int r = g * 256 + h;
    float wd = (k < 256) ? dWhh[r * 256 + k] : dWih[r * 257 + (k - 256)];
    g_Wdec[idx] = wd;
    if (k < 257) {
        float we = (k < 256) ? eWhh[r * 256 + k] : eWih[r];
        g_Wenc[idx] = we;
    }
    if (k == 0) {
        g_bias_enc[j] = ebih[r] + ebhh[r];
        g_bias_dec[j] = dbih[r] + dbhh[r];
    }
}

__global__ void init_kernel()
{
    int idx = blockIdx.x * blockDim.x + threadIdx.x;
    if (idx < B * H) { g_hA[idx] = 0.f; g_c[idx] = 0.f; }
    if (idx < B)     { g_decnext[idx] = 0.f; }
}

__global__ void detect_y(const void* __restrict__ y)
{
    const int* yi = (const int*)y;
    int all0 = 1;
    for (int i = 1; i < 64; i += 2) if (yi[i] != 0) all0 = 0;
    g_y64 = all0;
}

// ---------------- ENCODER fused GEMM + LSTM pointwise (R16 exact) ----------
__global__ __launch_bounds__(256) void lstm_step(const float* __restrict__ xptr,
                                                 int KMAIN, int is_enc, int t, int parity)
{
    const float* h_in  = parity ? g_hB : g_hA;
    float*       h_out = parity ? g_hA : g_hB;
    const float* W     = g_Wenc;
    const float* bias  = g_bias_enc;

    __shared__ float Ab[2][32][36];
    __shared__ float Wb[2][32][64];

    int rb = blockIdx.y * 32, jc = blockIdx.x * 64;
    int tid = threadIdx.x;
    int tx = tid & 15, ty = tid >> 4;

    int arow = tid >> 3, aq = tid & 7;
    int wk0 = tid >> 4,           wq0 = tid & 15;
    int wk1 = (tid + 256) >> 4,   wq1 = (tid + 256) & 15;

    float acc[2][4] = {};
    float cmp[2][4] = {};

    cpa16(&Ab[0][arow][aq * 4], &h_in[(rb + arow) * 256 + aq * 4]);
    cpa16(&Wb[0][wk0][wq0 * 4], &W[wk0 * G4 + jc + wq0 * 4]);
    cpa16(&Wb[0][wk1][wq1 * 4], &W[wk1 * G4 + jc + wq1 * 4]);
    CPA_COMMIT();

    int T = KMAIN >> 5;
    for (int ti = 0; ti < T; ti++) {
        int kn = (ti + 1) << 5;
        bool have = (ti + 1 < T);
        int cb = ti & 1, nb = (ti + 1) & 1;

        if (have) {
            cpa16(&Ab[nb][arow][aq * 4], &h_in[(rb + arow) * 256 + kn + aq * 4]);
            cpa16(&Wb[nb][wk0][wq0 * 4], &W[(kn + wk0) * G4 + jc + wq0 * 4]);
            cpa16(&Wb[nb][wk1][wq1 * 4], &W[(kn + wk1) * G4 + jc + wq1 * 4]);
            CPA_COMMIT();
            CPA_WAIT1();
        } else {
            CPA_WAIT0();
        }
        __syncthreads();

        #pragma unroll
        for (int k8 = 0; k8 < 4; k8++) {
            float tmp[2][4] = {};
            #pragma unroll
            for (int kk = 0; kk < 8; kk++) {
                int k = k8 * 8 + kk;
                float4 w = *(const float4*)&Wb[cb][k][tx * 4];
                float a0 = Ab[cb][ty * 2 + 0][k];
                float a1 = Ab[cb][ty * 2 + 1][k];
                tmp[0][0] = fmaf(a0, w.x, tmp[0][0]);
                tmp[0][1] = fmaf(a0, w.y, tmp[0][1]);
                tmp[0][2] = fmaf(a0, w.z, tmp[0][2]);
                tmp[0][3] = fmaf(a0, w.w, tmp[0][3]);
                tmp[1][0] = fmaf(a1, w.x, tmp[1][0]);
                tmp[1][1] = fmaf(a1, w.y, tmp[1][1]);
                tmp[1][2] = fmaf(a1, w.z, tmp[1][2]);
                tmp[1][3] = fmaf(a1, w.w, tmp[1][3]);
            }
            #pragma unroll
            for (int r = 0; r < 2; r++)
                #pragma unroll
                for (int cq = 0; cq < 4; cq++)
                    KAHAN_ADD(acc[r][cq], cmp[r][cq], tmp[r][cq]);
        }
        __syncthreads();
    }

    int jb = jc + tx * 4;
    float4 wlast = *(const float4*)&W[KMAIN * G4 + jb];
    #pragma unroll
    for (int r = 0; r < 2; r++) {
        int b = rb + ty * 2 + r;
        float e = xptr[b * S + t];
        KAHAN_ADD(acc[r][0], cmp[r][0], e * wlast.x);
        KAHAN_ADD(acc[r][1], cmp[r][1], e * wlast.y);
        KAHAN_ADD(acc[r][2], cmp[r][2], e * wlast.z);
        KAHAN_ADD(acc[r][3], cmp[r][3], e * wlast.w);
    }

    int unit = (jc >> 2) + tx;
    float bi = bias[jb + 0], bf = bias[jb + 1], bg = bias[jb + 2], bo = bias[jb + 3];
    #pragma unroll
    for (int r = 0; r < 2; r++) {
        int b = rb + ty * 2 + r;
        float iv = sig_xla(acc[r][0] + bi);
        float fv = sig_xla(acc[r][1] + bf);
        float gv = tanh_xla(acc[r][2] + bg);
        float ov = sig_xla(acc[r][3] + bo);
        float cold = g_c[b * H + unit];
        float cn = fv * cold + iv * gv;
        float hh = ov * tanh_xla(cn);
        g_c[b * H + unit] = cn;
        h_out[b * H + unit] = hh;
        g_enc_out[b * (S * H) + t * H + unit] = hh;
    }
}

// ---------------- DECODER fused attn + h-half GEMM --------------------------
// 768 CTAs: [0,512) attn for batch b; [512,768) h-half GEMM (tiles 0..7).
__global__ __launch_bounds__(256) void attn_hgemm(const float* __restrict__ x,
                                                  const void* __restrict__ yv,
                                                  const float* __restrict__ W2,
                                                  const float* __restrict__ V,
                                                  float* __restrict__ outp,
                                                  int t, int parity, int do_gemm)
{
    const float* h_in = parity ? g_hB : g_hA;
    int tid = threadIdx.x;

    __shared__ float sh_h[256];
    __shared__ float sh_w2h[16];
    __shared__ float sV[16];
    __shared__ float sh_log[256];
    __shared__ float sh_aj[256];
    __shared__ float sh_red[256];
    __shared__ int   sh_idx[256];
    __shared__ float sgp[8][256];
    __shared__ float Ab[2][32][36];
    __shared__ float Wb[2][32][64];

    if (blockIdx.x >= B) {
        // ================= h-half GEMM (dec tiles 0..7) =================
        if (!do_gemm) return;
        const float* W = g_Wdec;
        int cidx = blockIdx.x - B;
        int jc = (cidx & 15) * 64, rb = (cidx >> 4) * 32;
        int tx = tid & 15, ty = tid >> 4;

        int arow = tid >> 3, aq = tid & 7;
        int wk0 = tid >> 4,           wq0 = tid & 15;
        int wk1 = (tid + 256) >> 4,   wq1 = (tid + 256) & 15;

        float acc[2][4] = {};
        float cmp[2][4] = {};

        cpa16(&Ab[0][arow][aq * 4], &h_in[(rb + arow) * 256 + aq * 4]);
        cpa16(&Wb[0][wk0][wq0 * 4], &W[wk0 * G4 + jc + wq0 * 4]);
        cpa16(&Wb[0][wk1][wq1 * 4], &W[wk1 * G4 + jc + wq1 * 4]);
        CPA_COMMIT();

        for (int ti = 0; ti < 8; ti++) {
            int kn = (ti + 1) << 5;
            bool have = (ti < 7);
            int cb = ti & 1, nb = (ti + 1) & 1;
            if (have) {
                cpa16(&Ab[nb][arow][aq * 4], &h_in[(rb + arow) * 256 + kn + aq * 4]);
                cpa16(&Wb[nb][wk0][wq0 * 4], &W[(kn + wk0) * G4 + jc + wq0 * 4]);
                cpa16(&Wb[nb][wk1][wq1 * 4], &W[(kn + wk1) * G4 + jc + wq1 * 4]);
                CPA_COMMIT();
                CPA_WAIT1();
            } else {
                CPA_WAIT0();
            }
            __syncthreads();
            #pragma unroll
            for (int k8 = 0; k8 < 4; k8++) {
                float tmp[2][4] = {};
                #pragma unroll
                for (int kk = 0; kk < 8; kk++) {
                    int k = k8 * 8 + kk;
                    float4 w = *(const float4*)&Wb[cb][k][tx * 4];
                    float a0 = Ab[cb][ty * 2 + 0][k];
                    float a1 = Ab[cb][ty * 2 + 1][k];
                    tmp[0][0] = fmaf(a0, w.x, tmp[0][0]);
                    tmp[0][1] = fmaf(a0, w.y, tmp[0][1]);
                    tmp[0][2] = fmaf(a0, w.z, tmp[0][2]);
                    tmp[0][3] = fmaf(a0, w.w, tmp[0][3]);
                    tmp[1][0] = fmaf(a1, w.x, tmp[1][0]);
                    tmp[1][1] = fmaf(a1, w.y, tmp[1][1]);
                    tmp[1][2] = fmaf(a1, w.z, tmp[1][2]);
                    tmp[1][3] = fmaf(a1, w.w, tmp[1][3]);
                }
                #pragma unroll
                for (int r = 0; r < 2; r++)
                    #pragma unroll
                    for (int cq = 0; cq < 4; cq++)
                        KAHAN_ADD(acc[r][cq], cmp[r][cq], tmp[r][cq]);
            }
            __syncthreads();
        }

        int jb = jc + tx * 4;
        #pragma unroll
        for (int r = 0; r < 2; r++) {
            int b = rb + ty * 2 + r;
            *(float4*)&g_pacc[b * G4 + jb] = make_float4(acc[r][0], acc[r][1], acc[r][2], acc[r][3]);
            *(float4*)&g_pcmp[b * G4 + jb] = make_float4(cmp[r][0], cmp[r][1], cmp[r][2], cmp[r][3]);
        }
        return;
    }

    // ================= attention for batch b (R16 exact) =================
    int b = blockIdx.x;

    sh_h[tid] = h_in[b * H + tid];
    if (tid == 0) g_ext[b * 257 + 256] = g_decnext[b];
    if (tid < U)  sV[tid] = V[tid];
    __syncthreads();

    int wid = tid >> 5, lane = tid & 31;
    for (int u = wid; u < U; u += 8) {
        float p = 0.f, c = 0.f;
        #pragma unroll
        for (int k = lane; k < 256; k += 32) KAHAN_ADD(p, c, sh_h[k] * W2[u * 256 + k]);
        #pragma unroll
        for (int o = 16; o; o >>= 1) p += __shfl_xor_sync(0xffffffffu, p, o);
        if (lane == 0) sh_w2h[u] = p;
    }
    __syncthreads();

    const float* ew = g_encW1 + b * (U * S) + tid;
    float lg = 0.f, lgc = 0.f;
    #pragma unroll
    for (int u = 0; u < U; u++)
        KAHAN_ADD(lg, lgc, sV[u] * tanh_xla(ew[u * S] + sh_w2h[u]));
    sh_log[tid] = lg;
    sh_red[tid] = lg;
    sh_idx[tid] = tid;
    __syncthreads();

    // argmax (first occurrence on ties)
    #pragma unroll
    for (int off = 128; off; off >>= 1) {
        if (tid < off) {
            float ov = sh_red[tid + off]; int oi = sh_idx[tid + off];
            float cv = sh_red[tid];       int ci = sh_idx[tid];
            if (ov > cv || (ov == cv && oi < ci)) { sh_red[tid] = ov; sh_idx[tid] = oi; }
        }
        __syncthreads();
    }
    float mx = sh_red[0]; int mi = sh_idx[0];
    __syncthreads();

    float p = exp_p(lg - mx);
    sh_red[tid] = p;
    __syncthreads();
    #pragma unroll
    for (int off = 128; off; off >>= 1) {
        if (tid < off) sh_red[tid] += sh_red[tid + off];
        __syncthreads();
    }
    float sum = sh_red[0];
    sh_aj[tid] = __fdiv_rn(p, sum);

    if (tid == 0) {
        int yi = g_y64 ? (int)((const long long*)yv)[b * S + t]
                       : ((const int*)yv)[b * S + t];
        float logpy = sh_log[yi] - mx - (float)log((double)sum);
        g_lossbuf[t * B + b] = -logpy;
        outp[t * B + b] = (float)mi;
        g_decnext[b] = x[b * S + yi];
    }
    __syncthreads();

    // di[b][h] = sum_s aj[s] * enc_out[b][s][h]
    {
        int hc = tid & 31;
        int sg = tid >> 5;
        const float* eb = g_enc_out + (size_t)b * (S * H) + hc * 8;
        float a[8] = {}, cc[8] = {};
        int sbase = sg * 32;
        bool persist = (b < B_PERSIST);
        #pragma unroll
        for (int c8 = 0; c8 < 4; c8++) {
            float tmp[8] = {};
            #pragma unroll
            for (int kk = 0; kk < 8; kk++) {
                int s2 = sbase + c8 * 8 + kk;
                float e[8];
                if (persist) ld8_last(eb + (size_t)s2 * H, e);
                else         ld8_first(eb + (size_t)s2 * H, e);
                float aw = sh_aj[s2];
                #pragma unroll
                for (int j = 0; j < 8; j++) tmp[j] = fmaf(aw, e[j], tmp[j]);
            }
            #pragma unroll
            for (int j = 0; j < 8; j++) KAHAN_ADD(a[j], cc[j], tmp[j]);
        }
        #pragma unroll
        for (int j = 0; j < 8; j++) sgp[sg][hc * 8 + j] = a[j];
    }
    __syncthreads();
    {
        float a = sgp[0][tid], c = 0.f;
        #pragma unroll
        for (int g = 1; g < 8; g++) KAHAN_ADD(a, c, sgp[g][tid]);
        g_ext[b * 257 + tid] = a;
    }
}

// ---------------- DECODER second half: ext tiles 8..15 + epilogue -----------
// Resumes the (acc,cmp) Kahan stream; flattened order == R16 monolith.
__global__ __launch_bounds__(256) void dec_gemm2(int parity)
{
    float*       h_out = parity ? g_hA : g_hB;
    const float* W     = g_Wdec;
    const float* bias  = g_bias_dec;

    __shared__ float Ab[2][32][36];
    __shared__ float Wb[2][32][64];

    int rb = blockIdx.y * 32, jc = blockIdx.x * 64;
    int tid = threadIdx.x;
    int tx = tid & 15, ty = tid >> 4;

    int wk0 = tid >> 4,           wq0 = tid & 15;
    int wk1 = (tid + 256) >> 4,   wq1 = (tid + 256) & 15;

    int jb = jc + tx * 4;
    float acc[2][4], cmp[2][4];
    #pragma unroll
    for (int r = 0; r < 2; r++) {
        int b = rb + ty * 2 + r;
        float4 a = *(const float4*)&g_pacc[b * G4 + jb];
        float4 c = *(const float4*)&g_pcmp[b * G4 + jb];
        acc[r][0] = a.x; acc[r][1] = a.y; acc[r][2] = a.z; acc[r][3] = a.w;
        cmp[r][0] = c.x; cmp[r][1] = c.y; cmp[r][2] = c.z; cmp[r][3] = c.w;
    }

    // issue ext tile 0 (global k 256..287)
    #pragma unroll
    for (int l = 0; l < 4; l++) {
        int idx = tid + l * 256;
        int k = idx & 31, r = idx >> 5;
        cpa4(&Ab[0][r][k], &g_ext[(rb + r) * 257 + k]);
    }
    cpa16(&Wb[0][wk0][wq0 * 4], &W[(256 + wk0) * G4 + jc + wq0 * 4]);
    cpa16(&Wb[0][wk1][wq1 * 4], &W[(256 + wk1) * G4 + jc + wq1 * 4]);
    CPA_COMMIT();

    for (int ti = 0; ti < 8; ti++) {
        int kn = (ti + 1) << 5;           // local ext col base of next tile
        bool have = (ti < 7);
        int cb = ti & 1, nb = (ti + 1) & 1;
        if (have) {
            #pragma unroll
            for (int l = 0; l < 4; l++) {
                int idx = tid + l * 256;
                int k = idx & 31, r = idx >> 5;
                cpa4(&Ab[nb][r][k], &g_ext[(rb + r) * 257 + kn + k]);
            }
            cpa16(&Wb[nb][wk0][wq0 * 4], &W[(256 + kn + wk0) * G4 + jc + wq0 * 4]);
            cpa16(&Wb[nb][wk1][wq1 * 4], &W[(256 + kn + wk1) * G4 + jc + wq1 * 4]);
            CPA_COMMIT();
            CPA_WAIT1();
        } else {
            CPA_WAIT0();
        }
        __syncthreads();
        #pragma unroll
        for (int k8 = 0; k8 < 4; k8++) {
            float tmp[2][4] = {};
            #pragma unroll
            for (int kk = 0; kk < 8; kk++) {
                int k = k8 * 8 + kk;
                float4 w = *(const float4*)&Wb[cb][k][tx * 4];
                float a0 = Ab[cb][ty * 2 + 0][k];
                float a1 = Ab[cb][ty * 2 + 1][k];
                tmp[0][0] = fmaf(a0, w.x, tmp[0][0]);
                tmp[0][1] = fmaf(a0, w.y, tmp[0][1]);
                tmp[0][2] = fmaf(a0, w.z, tmp[0][2]);
                tmp[0][3] = fmaf(a0, w.w, tmp[0][3]);
                tmp[1][0] = fmaf(a1, w.x, tmp[1][0]);
                tmp[1][1] = fmaf(a1, w.y, tmp[1][1]);
                tmp[1][2] = fmaf(a1, w.z, tmp[1][2]);
                tmp[1][3] = fmaf(a1, w.w, tmp[1][3]);
            }
            #pragma unroll
            for (int r = 0; r < 2; r++)
                #pragma unroll
                for (int cq = 0; cq < 4; cq++)
                    KAHAN_ADD(acc[r][cq], cmp[r][cq], tmp[r][cq]);
        }
        __syncthreads();
    }

    // ---- final scalar input column (dec_in) ----
    float4 wlast = *(const float4*)&W[512 * G4 + jb];
    #pragma unroll
    for (int r = 0; r < 2; r++) {
        int b = rb + ty * 2 + r;
        float e = g_ext[b * 257 + 256];
        KAHAN_ADD(acc[r][0], cmp[r][0], e * wlast.x);
        KAHAN_ADD(acc[r][1], cmp[r][1], e * wlast.y);
        KAHAN_ADD(acc[r][2], cmp[r][2], e * wlast.z);
        KAHAN_ADD(acc[r][3], cmp[r][3], e * wlast.w);
    }

    int unit = (jc >> 2) + tx;
    float bi = bias[jb + 0], bf = bias[jb + 1], bg = bias[jb + 2], bo = bias[jb + 3];
    #pragma unroll
    for (int r = 0; r < 2; r++) {
        int b = rb + ty * 2 + r;
        float iv = sig_xla(acc[r][0] + bi);
        float fv = sig_xla(acc[r][1] + bf);
        float gv = tanh_xla(acc[r][2] + bg);
        float ov = sig_xla(acc[r][3] + bo);
        float cold = g_c[b * H + unit];
        float cn = fv * cold + iv * gv;
        float hh = ov * tanh_xla(cn);
        g_c[b * H + unit] = cn;
        h_out[b * H + unit] = hh;
    }
}

// ---------------- encW1 precompute: [b][u][s] = enc_out[b,s,:] . W1[u,:] ----
__global__ __launch_bounds__(256) void encW1_kernel(const float* __restrict__ W1)
{
    int w = blockIdx.x * 8 + (threadIdx.x >> 5);
    int lane = threadIdx.x & 31;
    int b = w >> 8, s = w & 255;
    const float* e = g_enc_out + b * (S * H) + s * H;
    float ev[8];
    #pragma unroll
    for (int i = 0; i < 8; i++) ev[i] = e[lane + 32 * i];
    #pragma unroll
    for (int u = 0; u < U; u++) {
        float p = 0.f, c = 0.f;
        #pragma unroll
        for (int i = 0; i < 8; i++) KAHAN_ADD(p, c, ev[i] * W1[u * 256 + lane + 32 * i]);
        #pragma unroll
        for (int o = 16; o; o >>= 1) p += __shfl_xor_sync(0xffffffffu, p, o);
        if (lane == 0) g_encW1[b * (U * S) + u * S + s] = p;
    }
}

// ---------------- deterministic loss reduction ------------------------------
__global__ void loss_reduce(float* __restrict__ outp, int do_write)
{
    __shared__ float sr[256];
    int tid = threadIdx.x;
    float a = 0.f, c = 0.f;
    for (int i = tid; i < S * B; i += 256) KAHAN_ADD(a, c, g_lossbuf[i]);
    sr[tid] = a;
    __syncthreads();
    #pragma unroll
    for (int off = 128; off; off >>= 1) {
        if (tid < off) sr[tid] += sr[tid + off];
        __syncthreads();
    }
    if (tid == 0 && do_write) outp[S * B] = __fdiv_rn(sr[0], 512.f * 512.f);
}

// ---------------- host launch ----------------------------------------------
extern "C" void kernel_launch(void* const* d_in, const int* in_sizes, int n_in,
                              void* d_out, int out_size)
{
    const float* x    = (const float*)d_in[0];
    const void*  y    = d_in[1];
    const float* eWih = (const float*)d_in[2];
    const float* eWhh = (const float*)d_in[3];
    const float* ebih = (const float*)d_in[4];
    const float* ebhh = (const float*)d_in[5];
    const float* dWih = (const float*)d_in[6];
    const float* dWhh = (const float*)d_in[7];
    const float* dbih = (const float*)d_in[8];
    const float* dbhh = (const float*)d_in[9];
    const float* W1   = (const float*)d_in[10];
    const float* W2   = (const float*)d_in[11];
    const float* V    = (const float*)d_in[12];
    float* outp = (float*)d_out;

    prep_kernel<<<(513 * G4 + 255) / 256, 256>>>(eWih, eWhh, ebih, ebhh,
                                                 dWih, dWhh, dbih, dbhh);
    init_kernel<<<(B * H + 255) / 256, 256>>>();
    detect_y<<<1, 1>>>(y);

    dim3 egrid(G4 / 64, B / 32);   // 16 x 16 = 256 CTAs

    // encoder (KMAIN=256, x_t handled in epilogue)
    for (int t = 0; t < S; t++)
        lstm_step<<<egrid, 256>>>(x, 256, 1, t, t & 1);

    encW1_kernel<<<B * S / 8, 256>>>(W1);

    // decoder: attn fused with the independent h-half GEMM in one grid,
    // then dec_gemm2 finishes the ext half + epilogue. t=255 lstm unused.
    for (int t = 0; t < S; t++) {
        int dg = (t < S - 1) ? 1 : 0;
        attn_hgemm<<<B + 256, 256>>>(x, y, W2, V, outp, t, t & 1, dg);
        if (dg) dec_gemm2<<<egrid, 256>>>(t & 1);
    }

    loss_reduce<<<1, 256>>>(outp, out_size > S * B ? 1 : 0);
}